// round 17
// baseline (speedup 1.0000x reference)
#include <cuda_runtime.h>
#include <cuda_fp16.h>
#include <cstdint>

// CFConv fused, FP16 mma (m16n8k16). Persistent CTAs; weights in smem once;
// rbf via warp-private cp.async ring (depth 3) running across tile boundaries.
// NEW vs R15: epilogue transposed through a warp-private smem scratch so the
// nf gather (LDG.128) and out scatter (red.v4) are ROW-COALESCED — cuts
// epilogue L1 wavefronts ~6x (each instruction touches 4 lines, not 32).
//
// h  = softplus_b05(rbf @ W1^T + b1)   [E,128] x [64,128]^T -> [E,64]
// g  = h @ W2^T + b2                   [E,64]  x [64,64]^T  -> [E,64]
// out[dst[e]] += node_feats[src[e]] * g[e]

constexpr int BM      = 128;
constexpr int THREADS = 128;

constexpr int W1S  = 68;    // half2 words per W1 row (64 + 4 pad)
constexpr int W2S  = 36;    // half2 words per W2 row (32 + 4 pad)
constexpr int AROW = 20;    // fp32 words per A row (16 + 4 pad)
constexpr int RING = 3;     // chunks in flight per warp
constexpr int GROW = 36;    // scratch row stride in words (32 half2 + 4 pad)

__device__ uint32_t g_W1h[64 * W1S];
__device__ uint32_t g_W2h[64 * W2S];

constexpr int OFF_W1  = 0;
constexpr int OFF_W2  = OFF_W1 + 64 * W1S;        // 4352 words
constexpr int OFF_A   = OFF_W2 + 64 * W2S;        // 6656 words
constexpr int SLOTW   = 32 * AROW;                // 640 words per ring slot
constexpr int AWARP   = RING * SLOTW;             // 1920 words per warp
constexpr int OFF_SCR = OFF_A + 4 * AWARP;        // 14336 words
constexpr int SCRW    = 32 * GROW;                // 1152 words per warp
constexpr int SMEM_WORDS = OFF_SCR + 4 * SCRW;    // 18944
constexpr int SMEM_BYTES = SMEM_WORDS * 4;        // 75776 -> 3 CTAs/SM
constexpr int SLOTB = SLOTW * 4;                  // 2560 B

// setup: zero output + convert weights to fp16 padded layout
__global__ void setup_kernel(float4* out4, int n4,
                             const float* __restrict__ W1,
                             const float* __restrict__ W2) {
    int i = blockIdx.x * blockDim.x + threadIdx.x;
    if (i < n4) out4[i] = make_float4(0.f, 0.f, 0.f, 0.f);
    if (i < 64 * W1S) {
        int row = i / W1S, c = i % W1S;
        uint32_t v = 0;
        if (c < 64) {
            __half2 h = __floats2half2_rn(W1[row * 128 + 2 * c], W1[row * 128 + 2 * c + 1]);
            v = *reinterpret_cast<uint32_t*>(&h);
        }
        g_W1h[i] = v;
    }
    if (i < 64 * W2S) {
        int row = i / W2S, c = i % W2S;
        uint32_t v = 0;
        if (c < 32) {
            __half2 h = __floats2half2_rn(W2[row * 64 + 2 * c], W2[row * 64 + 2 * c + 1]);
            v = *reinterpret_cast<uint32_t*>(&h);
        }
        g_W2h[i] = v;
    }
}

__device__ __forceinline__ float softplus_b05(float x) {
    float hx = 0.5f * x;
    return (hx > 14.0f) ? x : 2.0f * __logf(1.0f + __expf(hx));
}

__device__ __forceinline__ uint32_t pack_h2(float lo, float hi) {
    __half2 p = __floats2half2_rn(lo, hi);
    return *reinterpret_cast<uint32_t*>(&p);
}

__device__ __forceinline__ void mma_f16(float c[4], const uint32_t a[4],
                                        uint32_t b0, uint32_t b1) {
    asm volatile(
        "mma.sync.aligned.m16n8k16.row.col.f32.f16.f16.f32 "
        "{%0,%1,%2,%3}, {%4,%5,%6,%7}, {%8,%9}, {%0,%1,%2,%3};"
        : "+f"(c[0]), "+f"(c[1]), "+f"(c[2]), "+f"(c[3])
        : "r"(a[0]), "r"(a[1]), "r"(a[2]), "r"(a[3]), "r"(b0), "r"(b1));
}

__device__ __forceinline__ void ldsm_x4(uint32_t r[4], uint32_t addr) {
    asm volatile("ldmatrix.sync.aligned.m8n8.x4.shared.b16 {%0,%1,%2,%3}, [%4];"
                 : "=r"(r[0]), "=r"(r[1]), "=r"(r[2]), "=r"(r[3]) : "r"(addr));
}

__device__ __forceinline__ void cp_async16(uint32_t saddr, const void* gsrc) {
    asm volatile("cp.async.cg.shared.global [%0], [%1], 16;"
                 :: "r"(saddr), "l"(gsrc));
}

__device__ __forceinline__ float2 lds_f2(uint32_t addr) {
    float2 v;
    asm volatile("ld.shared.v2.f32 {%0,%1}, [%2];"
                 : "=f"(v.x), "=f"(v.y) : "r"(addr));
    return v;
}

__device__ __forceinline__ void sts32(uint32_t addr, uint32_t v) {
    asm volatile("st.shared.b32 [%0], %1;" :: "r"(addr), "r"(v));
}

__device__ __forceinline__ uint2 lds_u2(uint32_t addr) {
    uint2 v;
    asm volatile("ld.shared.v2.b32 {%0,%1}, [%2];"
                 : "=r"(v.x), "=r"(v.y) : "r"(addr));
    return v;
}

__global__ void __launch_bounds__(THREADS, 3) cfconv_f16_kernel(
    const float* __restrict__ rbf,   // [E,128]
    const float* __restrict__ nf,    // [N,64]
    const int*   __restrict__ src,   // [E]
    const int*   __restrict__ dst,   // [E]
    const float* __restrict__ b1,    // [64]
    const float* __restrict__ b2,    // [64]
    float*       __restrict__ out,   // [N,64]
    int E, int ntiles)
{
    extern __shared__ uint32_t smem[];

    const int tid  = threadIdx.x;
    const int lane = tid & 31;
    const int warp = tid >> 5;
    const int gr   = lane >> 2;
    const int gc   = lane & 3;
    const int wrow = warp * 32;
    const int gstride = gridDim.x;
    const unsigned FULL = 0xffffffffu;

    const uint32_t sbase = (uint32_t)__cvta_generic_to_shared(smem);

    // ---- group 0: weights, loaded ONCE per persistent CTA ----
    for (int i = tid; i < 1088; i += THREADS)
        cp_async16(sbase + OFF_W1 * 4 + i * 16, (const char*)g_W1h + i * 16);
    for (int i = tid; i < 576; i += THREADS)
        cp_async16(sbase + OFF_W2 * 4 + i * 16, (const char*)g_W2h + i * 16);
    asm volatile("cp.async.commit_group;");

    // ---- ring geometry: lane covers rows (lane>>2)+8i, 16B each ----
    const uint32_t aBase = sbase + (OFF_A + warp * AWARP) * 4;
    const uint32_t scr   = sbase + (OFF_SCR + warp * SCRW) * 4;
    const int lrow = lane >> 2;
    uint32_t sdst4[4];
    #pragma unroll
    for (int i = 0; i < 4; i++)
        sdst4[i] = aBase + ((lrow + 8 * i) * AROW + (lane & 3) * 4) * 4;

    // ---- B-fragment ldsm addresses ----
    const int lb = ((lane >> 4) << 3) | (lane & 7);
    const int sbyt = ((lane >> 3) & 1) * 16;
    uint32_t bW1a[4], bW2a[4];
    #pragma unroll
    for (int p = 0; p < 4; p++) {
        bW1a[p] = sbase + (OFF_W1 + (p * 16 + lb) * W1S) * 4 + sbyt;
        bW2a[p] = sbase + (OFF_W2 + (p * 16 + lb) * W2S) * 4 + sbyt;
    }

    // ---- first tile's row pointers; prime ring with its chunks 0..2 ----
    int tile = blockIdx.x;
    const float* rsrcN[4];
    #pragma unroll
    for (int i = 0; i < 4; i++) {
        long e = (long)tile * BM + wrow + lrow + 8 * i;
        rsrcN[i] = rbf + ((e < E) ? e : 0) * 128 + (lane & 3) * 4;
    }
    #pragma unroll
    for (int c = 0; c < RING; c++) {
        #pragma unroll
        for (int i = 0; i < 4; i++)
            cp_async16(sdst4[i] + c * SLOTB, rsrcN[i] + c * 16);
        asm volatile("cp.async.commit_group;");
    }

    asm volatile("cp.async.wait_group 3;");   // own weight parts done
    __syncthreads();                          // weights visible block-wide

    int slot = 0;

    for (; tile < ntiles; tile += gstride) {
        const float* rsrcC[4];
        #pragma unroll
        for (int i = 0; i < 4; i++) rsrcC[i] = rsrcN[i];
        {
            int tnext = tile + gstride;
            int tsrc = (tnext < ntiles) ? tnext : tile;
            #pragma unroll
            for (int i = 0; i < 4; i++) {
                long e = (long)tsrc * BM + wrow + lrow + 8 * i;
                rsrcN[i] = rbf + ((e < E) ? e : 0) * 128 + (lane & 3) * 4;
            }
        }

        // lane-private edge indices (lane = edge row)
        const long eMine = (long)tile * BM + wrow + lane;
        const bool valMine = (eMine < E);
        int myS = valMine ? src[eMine] : 0;
        int myD = valMine ? dst[eMine] : 0;

        // ---- GEMM1: 8 chunks of 16; replacement chunk issued each step ----
        float acc[2][8][4] = {};
        #pragma unroll
        for (int c = 0; c < 8; c++) {
            asm volatile("cp.async.wait_group 2;");
            __syncwarp();
            const uint32_t bo = slot * SLOTB;

            uint32_t a[2][4];
            #pragma unroll
            for (int mt = 0; mt < 2; mt++) {
                const uint32_t r0 = aBase + bo + ((mt * 16 + gr) * AROW + 2 * gc) * 4;
                const uint32_t r1 = r0 + 8 * AROW * 4;
                float2 f0 = lds_f2(r0);
                float2 f1 = lds_f2(r1);
                float2 f2 = lds_f2(r0 + 32);
                float2 f3 = lds_f2(r1 + 32);
                a[mt][0] = pack_h2(f0.x, f0.y);
                a[mt][1] = pack_h2(f1.x, f1.y);
                a[mt][2] = pack_h2(f2.x, f2.y);
                a[mt][3] = pack_h2(f3.x, f3.y);
            }

            __syncwarp();
            {
                const float* const* rs = (c + RING < 8) ? rsrcC : rsrcN;
                const int cc = (c + RING) & 7;
                #pragma unroll
                for (int i = 0; i < 4; i++)
                    cp_async16(sdst4[i] + bo, rs[i] + cc * 16);
                asm volatile("cp.async.commit_group;");
            }
            slot = (slot == RING - 1) ? 0 : slot + 1;

            #pragma unroll
            for (int p = 0; p < 4; p++) {
                uint32_t bb[4];
                ldsm_x4(bb, bW1a[p] + c * 32);
                mma_f16(acc[0][2 * p],     a[0], bb[0], bb[1]);
                mma_f16(acc[1][2 * p],     a[1], bb[0], bb[1]);
                mma_f16(acc[0][2 * p + 1], a[0], bb[2], bb[3]);
                mma_f16(acc[1][2 * p + 1], a[1], bb[2], bb[3]);
            }
        }

        // ---- bias + softplus + pack: GEMM1 C-frags -> GEMM2 A-frags ----
        uint32_t hA[2][4][4];
        #pragma unroll
        for (int kt = 0; kt < 4; kt++) {
            float bA0 = __ldg(b1 + kt * 16 + 2 * gc);
            float bA1 = __ldg(b1 + kt * 16 + 2 * gc + 1);
            float bB0 = __ldg(b1 + kt * 16 + 8 + 2 * gc);
            float bB1 = __ldg(b1 + kt * 16 + 8 + 2 * gc + 1);
            #pragma unroll
            for (int mt = 0; mt < 2; mt++) {
                const float* cA = acc[mt][2 * kt];
                const float* cB = acc[mt][2 * kt + 1];
                hA[mt][kt][0] = pack_h2(softplus_b05(cA[0] + bA0), softplus_b05(cA[1] + bA1));
                hA[mt][kt][1] = pack_h2(softplus_b05(cA[2] + bA0), softplus_b05(cA[3] + bA1));
                hA[mt][kt][2] = pack_h2(softplus_b05(cB[0] + bB0), softplus_b05(cB[1] + bB1));
                hA[mt][kt][3] = pack_h2(softplus_b05(cB[2] + bB0), softplus_b05(cB[3] + bB1));
            }
        }

        // ---- GEMM2: K=64, 4 chunks of 16 ----
        float acc2[2][8][4] = {};
        #pragma unroll
        for (int kt = 0; kt < 4; kt++) {
            #pragma unroll
            for (int p = 0; p < 4; p++) {
                uint32_t bb[4];
                ldsm_x4(bb, bW2a[p] + kt * 32);
                mma_f16(acc2[0][2 * p],     hA[0][kt], bb[0], bb[1]);
                mma_f16(acc2[1][2 * p],     hA[1][kt], bb[0], bb[1]);
                mma_f16(acc2[0][2 * p + 1], hA[0][kt], bb[2], bb[3]);
                mma_f16(acc2[1][2 * p + 1], hA[1][kt], bb[2], bb[3]);
            }
        }

        // ---- epilogue v2: fragment -> smem (fp16 g incl. b2), then
        //      row-coalesced nf gather + red.v4 scatter (2 rows per pass) ----
        #pragma unroll
        for (int nt = 0; nt < 8; nt++) {
            float bc0 = __ldg(b2 + nt * 8 + 2 * gc);
            float bc1 = __ldg(b2 + nt * 8 + 2 * gc + 1);
            #pragma unroll
            for (int mt = 0; mt < 2; mt++) {
                int r0 = mt * 16 + gr;
                uint32_t h0 = pack_h2(acc2[mt][nt][0] + bc0, acc2[mt][nt][1] + bc1);
                uint32_t h1 = pack_h2(acc2[mt][nt][2] + bc0, acc2[mt][nt][3] + bc1);
                sts32(scr + (r0 * GROW + nt * 4 + gc) * 4, h0);
                sts32(scr + ((r0 + 8) * GROW + nt * 4 + gc) * 4, h1);
            }
        }
        __syncwarp();

        const int rsel = lane >> 4;       // 0/1: which of the 2 rows this pass
        const int cq   = lane & 15;       // column quad (4 floats)
        #pragma unroll
        for (int p = 0; p < 16; p++) {
            int row = 2 * p + rsel;
            int s = __shfl_sync(FULL, myS, row);
            int d = __shfl_sync(FULL, myD, row);
            bool valid = ((long)tile * BM + wrow + row < E);
            // g: 4 halfs (8B) from scratch, row-coalesced
            uint2 gh = lds_u2(scr + (row * GROW + cq * 2) * 4);
            float2 glo = __half22float2(*reinterpret_cast<__half2*>(&gh.x));
            float2 ghi = __half22float2(*reinterpret_cast<__half2*>(&gh.y));
            if (valid) {
                // nf: 4 floats (16B) row-coalesced LDG.128
                float4 nf4 = *(const float4*)(nf + (long)s * 64 + cq * 4);
                float v0 = glo.x * nf4.x, v1 = glo.y * nf4.y;
                float v2 = ghi.x * nf4.z, v3 = ghi.y * nf4.w;
                asm volatile("red.global.add.v4.f32 [%0], {%1,%2,%3,%4};"
                             :: "l"(out + (long)d * 64 + cq * 4),
                                "f"(v0), "f"(v1), "f"(v2), "f"(v3) : "memory");
            }
        }
    }
}

extern "C" void kernel_launch(void* const* d_in, const int* in_sizes, int n_in,
                              void* d_out, int out_size) {
    const float* rbf = (const float*)d_in[0];
    const float* nf  = (const float*)d_in[1];
    const int*   src = (const int*)d_in[2];
    const int*   dst = (const int*)d_in[3];
    const float* W1  = (const float*)d_in[4];
    const float* b1  = (const float*)d_in[5];
    const float* W2  = (const float*)d_in[6];
    const float* b2  = (const float*)d_in[7];
    float* out = (float*)d_out;

    const int E = in_sizes[2];
    const int ntiles = (E + BM - 1) / BM;

    cudaFuncSetAttribute(cfconv_f16_kernel,
                         cudaFuncAttributeMaxDynamicSharedMemorySize, SMEM_BYTES);

    int n4 = out_size / 4;
    setup_kernel<<<(n4 + 255) / 256, 256>>>((float4*)out, n4, W1, W2);

    int grid = 148 * 3;
    if (grid > ntiles) grid = ntiles;
    cfconv_f16_kernel<<<grid, THREADS, SMEM_BYTES>>>(
        rbf, nf, src, dst, b1, b2, out, E, ntiles);
}